// round 17
// baseline (speedup 1.0000x reference)
#include <cuda_runtime.h>
#include <math.h>

// Problem constants
#define B_  2
#define T_  2048
#define C_  1024
#define H_  16
#define D_  64
#define M_  4096             // B*T
#define QKV_N 3072
#define K_  1024
#define KB_ (K_ / 8)         // 128 k-blocks of 8

// Scratch (allocation-free rule: __device__ globals)
__device__ float g_af[(size_t)M_ * C_];        // A-fragments (x, then O)
__device__ float g_wqkvF[(size_t)K_ * QKV_N];  // B-fragments of W_qkv
__device__ float g_wprojF[(size_t)K_ * C_];    // B-fragments of W_proj
__device__ float g_Qf[(size_t)M_ * C_];        // Q fragments (scale*log2e folded)
__device__ float g_Kf[(size_t)M_ * C_];        // K fragments
__device__ float g_Vf[(size_t)M_ * C_];        // V fragments

// ---------------------------------------------------------------------------
__device__ __forceinline__ unsigned f2tf32(float f) {
    unsigned u;
    asm("cvt.rna.tf32.f32 %0, %1;" : "=r"(u) : "f"(f));
    return u;
}
__device__ __forceinline__ float cvtf(float v) {
    return __uint_as_float(f2tf32(v));
}
__device__ __forceinline__ unsigned smem_u32(const void* p) {
    return (unsigned)__cvta_generic_to_shared(p);
}
#define CP_ASYNC16(dst, src) \
    asm volatile("cp.async.cg.shared.global [%0], [%1], 16;" \
                 :: "r"(dst), "l"(src))
#define CP_COMMIT()  asm volatile("cp.async.commit_group;")
#define CP_WAIT1()   asm volatile("cp.async.wait_group 1;")

#define MMA_TF32(acc, a0, a1, a2, a3, b0, b1) \
    asm volatile( \
        "mma.sync.aligned.m16n8k8.row.col.f32.tf32.tf32.f32 " \
        "{%0,%1,%2,%3},{%4,%5,%6,%7},{%8,%9},{%0,%1,%2,%3};" \
        : "+f"((acc)[0]), "+f"((acc)[1]), "+f"((acc)[2]), "+f"((acc)[3]) \
        : "r"(a0), "r"(a1), "r"(a2), "r"(a3), "r"(b0), "r"(b1))

// Q scale with log2(e) folded: softmax done in exp2 domain.
#define QSCALE (0.125f * 1.4426950408889634f)

// ---------------------------------------------------------------------------
// GEMM prep: row-major -> fragment order (tf32).
// ---------------------------------------------------------------------------
__global__ void prep_a_frag(const float* __restrict__ src, float* __restrict__ dst) {
    int q = blockIdx.x * blockDim.x + threadIdx.x;
    if (q >= M_ * K_ / 4) return;
    int l = q & 31;
    int rk = q >> 5;
    int kb = rk % KB_, rb = rk / KB_;
    int g = l >> 2, t = l & 3;
    int r0 = rb * 16 + g, c0 = kb * 8 + t;
    float4 o;
    o.x = cvtf(src[(size_t)r0 * K_ + c0]);
    o.y = cvtf(src[(size_t)(r0 + 8) * K_ + c0]);
    o.z = cvtf(src[(size_t)r0 * K_ + c0 + 4]);
    o.w = cvtf(src[(size_t)(r0 + 8) * K_ + c0 + 4]);
    reinterpret_cast<float4*>(dst)[q] = o;
}

__global__ void prep_b_frag(const float* __restrict__ W, float* __restrict__ dst, int N) {
    int q = blockIdx.x * blockDim.x + threadIdx.x;
    if (q >= N * K_ / 2) return;
    int l = q & 31;
    int ck = q >> 5;
    int kb = ck % KB_, cb = ck / KB_;
    int g = l >> 2, t = l & 3;
    int n = cb * 8 + g, k0 = kb * 8 + t;
    float2 o;
    o.x = cvtf(W[(size_t)k0 * N + n]);
    o.y = cvtf(W[(size_t)(k0 + 4) * N + n]);
    reinterpret_cast<float2*>(dst)[q] = o;
}

// ---------------------------------------------------------------------------
// Fragment-order tf32 GEMM, BK=32, 3-stage cp.async, reg double-buffered
// fragments. BM=BN=128; 256 thr = 8 warps (2x4); warp tile 64x32.
// mode 0: Cm = acc + bias (fp32, row-major)
// mode 1: QKV fused epilogue -> scatter cvtf(acc+bias) into Qf/Kf/Vf.
// ---------------------------------------------------------------------------
#define STAGE_FLOATS 8192
#define GSTG 3
#define GEMM_SMEM (GSTG * STAGE_FLOATS * 4)   // 96 KB

__global__ __launch_bounds__(256, 2) void gemm_frag_kernel(
        const float* __restrict__ A, const float* __restrict__ Bf,
        const float* __restrict__ bias, float* __restrict__ Cm,
        float* __restrict__ Qf, float* __restrict__ Kf, float* __restrict__ Vf,
        int N, int mode) {
    extern __shared__ float gsm[];

    const int tid  = threadIdx.x;
    const int lane = tid & 31;
    const int warp = tid >> 5;
    const int warpRow = warp >> 2;
    const int warpCol = warp & 3;
    const int g = lane >> 2, t = lane & 3;

    const int rb0 = blockIdx.y * 8;
    const int cb0 = blockIdx.x * 16;

    auto issue = [&](int s, int j) {
        float* As = gsm + s * STAGE_FLOATS;
        float* Bs = As + 4096;
        int kb0 = j * 4;
        #pragma unroll
        for (int i = 0; i < 4; i++) {
            int idx = tid + i * 256;
            {
                int chunk = idx >> 5, g32 = idx & 31;
                int rb = chunk >> 2, kb = chunk & 3;
                CP_ASYNC16(smem_u32(&As[(chunk * 32 + g32) * 4]),
                           &A[(((size_t)(rb0 + rb) * KB_ + kb0 + kb) * 32 + g32) * 4]);
            }
            {
                int chunk = idx >> 4, g16 = idx & 15;
                int cb = chunk >> 2, kb = chunk & 3;
                CP_ASYNC16(smem_u32(&Bs[(chunk * 16 + g16) * 4]),
                           &Bf[(((size_t)(cb0 + cb) * KB_ + kb0 + kb) * 16 + g16) * 4]);
            }
        }
    };

    float acc[4][4][4];
    #pragma unroll
    for (int i = 0; i < 4; i++)
        #pragma unroll
        for (int j = 0; j < 4; j++)
            #pragma unroll
            for (int r = 0; r < 4; r++) acc[i][j][r] = 0.f;

    issue(0, 0); CP_COMMIT();
    issue(1, 1); CP_COMMIT();

    unsigned a[2][4][4];
    unsigned b[2][4][2];

    const int nIter = K_ / 32;
    for (int it = 0; it < nIter; it++) {
        CP_WAIT1();
        __syncthreads();
        if (it + 2 < nIter) issue((it + 2) % GSTG, it + 2);
        CP_COMMIT();

        const float* As = gsm + (it % GSTG) * STAGE_FLOATS;
        const float* Bs = As + 4096;

        auto ldfrag = [&](int buf, int ks) {
            #pragma unroll
            for (int mt = 0; mt < 4; mt++) {
                int rb = warpRow * 4 + mt;
                float4 av = *reinterpret_cast<const float4*>(
                    &As[((rb * 4 + ks) * 32 + lane) * 4]);
                a[buf][mt][0] = __float_as_uint(av.x);
                a[buf][mt][1] = __float_as_uint(av.y);
                a[buf][mt][2] = __float_as_uint(av.z);
                a[buf][mt][3] = __float_as_uint(av.w);
            }
            #pragma unroll
            for (int nt = 0; nt < 4; nt++) {
                int cb = warpCol * 4 + nt;
                float2 bv = *reinterpret_cast<const float2*>(
                    &Bs[(cb * 4 + ks) * 64 + g * 8 + t * 2]);
                b[buf][nt][0] = __float_as_uint(bv.x);
                b[buf][nt][1] = __float_as_uint(bv.y);
            }
        };

        ldfrag(0, 0);
        #pragma unroll
        for (int ks = 0; ks < 4; ks++) {
            if (ks < 3) ldfrag((ks + 1) & 1, ks + 1);
            const int cur = ks & 1;
            #pragma unroll
            for (int mt = 0; mt < 4; mt++)
                #pragma unroll
                for (int nt = 0; nt < 4; nt++)
                    MMA_TF32(acc[mt][nt],
                             a[cur][mt][0], a[cur][mt][1],
                             a[cur][mt][2], a[cur][mt][3],
                             b[cur][nt][0], b[cur][nt][1]);
        }
    }

    if (mode == 0) {
        #pragma unroll
        for (int mt = 0; mt < 4; mt++) {
            int m0 = rb0 * 16 + warpRow * 64 + mt * 16 + g;
            #pragma unroll
            for (int nt = 0; nt < 4; nt++) {
                int n0 = cb0 * 8 + warpCol * 32 + nt * 8 + t * 2;
                Cm[(size_t)m0 * N + n0    ] = acc[mt][nt][0] + bias[n0];
                Cm[(size_t)m0 * N + n0 + 1] = acc[mt][nt][1] + bias[n0 + 1];
                Cm[(size_t)(m0 + 8) * N + n0    ] = acc[mt][nt][2] + bias[n0];
                Cm[(size_t)(m0 + 8) * N + n0 + 1] = acc[mt][nt][3] + bias[n0 + 1];
            }
        }
    } else {
        // QKV fused epilogue: scatter into fragment arrays.
        const int sec = (cb0 * 8) >> 10;
        #pragma unroll
        for (int mt = 0; mt < 4; mt++) {
            #pragma unroll
            for (int nt = 0; nt < 4; nt++) {
                #pragma unroll
                for (int r = 0; r < 4; r++) {
                    int row = rb0 * 16 + warpRow * 64 + mt * 16 + g
                            + ((r >> 1) << 3);
                    int col = cb0 * 8 + warpCol * 32 + nt * 8 + t * 2 + (r & 1);
                    float v = cvtf(acc[mt][nt][r] + bias[col]);
                    int bb = row >> 11, tp = row & 2047;
                    int hc = col & 1023, h = hc >> 6, c = hc & 63;
                    int bh = bb * 16 + h;
                    if (sec == 0) {
                        int tb = tp >> 4, g2 = tp & 7, rh = (tp >> 3) & 1;
                        int kk = c >> 3, cl = c & 7;
                        size_t addr =
                            ((((size_t)bh * 128 + tb) * 8 + kk) * 32
                             + g2 * 4 + (cl & 3)) * 4 + rh + 2 * (cl >> 2);
                        Qf[addr] = v * QSCALE;
                    } else if (sec == 1) {
                        int kt = tp >> 6, n8 = (tp >> 3) & 7, g2 = tp & 7;
                        int kk = c >> 3, cl = c & 7;
                        size_t addr =
                            (((((size_t)bh * 32 + kt) * 8 + n8) * 8 + kk) * 32
                             + g2 * 4 + (cl & 3)) * 2 + (cl >> 2);
                        Kf[addr] = v;
                    } else {
                        int kt = tp >> 6, kkv = (tp >> 3) & 7;
                        int tsv = tp & 3, th = (tp >> 2) & 1;
                        int d = c >> 3, g2 = c & 7;
                        size_t addr =
                            (((((size_t)bh * 32 + kt) * 8 + d) * 8 + kkv) * 32
                             + g2 * 4 + tsv) * 2 + th;
                        Vf[addr] = v;
                    }
                }
            }
        }
    }
}

// ---------------------------------------------------------------------------
// Attention v4: fragment Q/K/V, Q in regs, cp.async double buffer,
// heavy-first blocks, exp2-domain softmax, fused proj-A-fragment epilogue.
// ---------------------------------------------------------------------------
#define ATT_STAGE 8192
#define ATT_PS (16 * 68)
#define ATT_SMEM ((2 * ATT_STAGE + 8 * ATT_PS) * 4)

__global__ __launch_bounds__(256, 2) void attn_v4_kernel(
        const float* __restrict__ Qf, const float* __restrict__ Kf,
        const float* __restrict__ Vf, float* __restrict__ af) {
    int qt = (gridDim.x - 1) - blockIdx.x;    // heavy blocks first
    int h  = blockIdx.y;
    int b  = blockIdx.z;
    int bh = b * H_ + h;

    extern __shared__ float asm_[];

    const int tid  = threadIdx.x;
    const int lane = tid & 31;
    const int warp = tid >> 5;
    const int g = lane >> 2, t = lane & 3;
    const int m0 = warp * 16;
    const int q0 = qt * 128;

    unsigned q[8][4];
    {
        const float4* qsrc = reinterpret_cast<const float4*>(Qf)
                           + ((size_t)bh * 128 + qt * 8 + warp) * 256;
        #pragma unroll
        for (int kk = 0; kk < 8; kk++) {
            float4 v = qsrc[kk * 32 + lane];
            q[kk][0] = __float_as_uint(v.x);
            q[kk][1] = __float_as_uint(v.y);
            q[kk][2] = __float_as_uint(v.z);
            q[kk][3] = __float_as_uint(v.w);
        }
    }

    float o[8][4];
    #pragma unroll
    for (int d = 0; d < 8; d++)
        #pragma unroll
        for (int r = 0; r < 4; r++) o[d][r] = 0.f;
    float mRow[2] = {-INFINITY, -INFINITY};
    float lRow[2] = {0.f, 0.f};

    auto issue = [&](int s, int kt) {
        const float4* ks = reinterpret_cast<const float4*>(Kf)
                         + ((size_t)bh * 32 + kt) * 1024;
        const float4* vs = reinterpret_cast<const float4*>(Vf)
                         + ((size_t)bh * 32 + kt) * 1024;
        unsigned dK = smem_u32(asm_ + s * ATT_STAGE);
        unsigned dV = dK + 4096 * 4;
        #pragma unroll
        for (int i = 0; i < 4; i++) {
            int idx = tid + i * 256;
            CP_ASYNC16(dK + idx * 16, ks + idx);
            CP_ASYNC16(dV + idx * 16, vs + idx);
        }
    };

    const int ktMax = 2 * qt + 1;
    issue(0, 0); CP_COMMIT();

    for (int kt = 0; kt <= ktMax; kt++) {
        if (kt < ktMax) issue((kt + 1) & 1, kt + 1);
        CP_COMMIT();
        CP_WAIT1();
        __syncthreads();

        int k0 = kt * 64;
        if (k0 <= q0 + m0 + 15) {
            const float* Ksm = asm_ + (kt & 1) * ATT_STAGE;
            const float* Vsm = Ksm + 4096;
            float* Psw = asm_ + 2 * ATT_STAGE + warp * ATT_PS;

            float s[8][4];
            #pragma unroll
            for (int n = 0; n < 8; n++)
                #pragma unroll
                for (int r = 0; r < 4; r++) s[n][r] = 0.f;

            #pragma unroll
            for (int kk = 0; kk < 8; kk++) {
                #pragma unroll
                for (int n = 0; n < 8; n++) {
                    float2 bv = *reinterpret_cast<const float2*>(
                        &Ksm[((n * 8 + kk) * 32 + lane) * 2]);
                    MMA_TF32(s[n], q[kk][0], q[kk][1], q[kk][2], q[kk][3],
                             __float_as_uint(bv.x), __float_as_uint(bv.y));
                }
            }

            if (k0 + 63 > q0 + m0) {
                int r0 = q0 + m0 + g, r1 = r0 + 8;
                #pragma unroll
                for (int n = 0; n < 8; n++) {
                    int c0 = k0 + n * 8 + 2 * t;
                    if (c0     > r0) s[n][0] = -INFINITY;
                    if (c0 + 1 > r0) s[n][1] = -INFINITY;
                    if (c0     > r1) s[n][2] = -INFINITY;
                    if (c0 + 1 > r1) s[n][3] = -INFINITY;
                }
            }

            // softmax in exp2 domain (log2e pre-folded into Q scale)
            #pragma unroll
            for (int half = 0; half < 2; half++) {
                float pm = -INFINITY;
                #pragma unroll
                for (int n = 0; n < 8; n++) {
                    pm = fmaxf(pm, s[n][2 * half]);
                    pm = fmaxf(pm, s[n][2 * half + 1]);
                }
                pm = fmaxf(pm, __shfl_xor_sync(0xffffffff, pm, 1));
                pm = fmaxf(pm, __shfl_xor_sync(0xffffffff, pm, 2));

                float mNew = fmaxf(mRow[half], pm);
                float alpha = exp2f(mRow[half] - mNew);
                float lsum = 0.f;
                #pragma unroll
                for (int n = 0; n < 8; n++) {
                    float p0 = exp2f(s[n][2 * half    ] - mNew);
                    float p1 = exp2f(s[n][2 * half + 1] - mNew);
                    s[n][2 * half    ] = p0;
                    s[n][2 * half + 1] = p1;
                    lsum += p0 + p1;
                }
                lsum += __shfl_xor_sync(0xffffffff, lsum, 1);
                lsum += __shfl_xor_sync(0xffffffff, lsum, 2);
                mRow[half] = mNew;
                lRow[half] = lRow[half] * alpha + lsum;
                #pragma unroll
                for (int n = 0; n < 8; n++) {
                    o[n][2 * half    ] *= alpha;
                    o[n][2 * half + 1] *= alpha;
                }
            }

            #pragma unroll
            for (int n = 0; n < 8; n++) {
                int c = n * 8 + 2 * t;
                float2 lo = { __uint_as_float(f2tf32(s[n][0])),
                              __uint_as_float(f2tf32(s[n][1])) };
                float2 hi = { __uint_as_float(f2tf32(s[n][2])),
                              __uint_as_float(f2tf32(s[n][3])) };
                *reinterpret_cast<float2*>(&Psw[g * 68 + c])       = lo;
                *reinterpret_cast<float2*>(&Psw[(g + 8) * 68 + c]) = hi;
            }
            __syncwarp();

            #pragma unroll
            for (int kk = 0; kk < 8; kk++) {
                unsigned a0 = __float_as_uint(Psw[g * 68       + kk * 8 + t    ]);
                unsigned a1 = __float_as_uint(Psw[(g + 8) * 68 + kk * 8 + t    ]);
                unsigned a2 = __float_as_uint(Psw[g * 68       + kk * 8 + t + 4]);
                unsigned a3 = __float_as_uint(Psw[(g + 8) * 68 + kk * 8 + t + 4]);
                #pragma unroll
                for (int d = 0; d < 8; d++) {
                    float2 bv = *reinterpret_cast<const float2*>(
                        &Vsm[((d * 8 + kk) * 32 + lane) * 2]);
                    MMA_TF32(o[d], a0, a1, a2, a3,
                             __float_as_uint(bv.x), __float_as_uint(bv.y));
                }
            }
        }
        __syncthreads();
    }

    // ---- epilogue: write proj A-fragments directly ----
    {
        int rbG = b * 128 + qt * 8 + warp;
        #pragma unroll
        for (int half = 0; half < 2; half++) {
            float inv = 1.0f / lRow[half];
            #pragma unroll
            for (int d = 0; d < 8; d++) {
                int kb = h * 8 + d;
                size_t basef = (((size_t)rbG * KB_ + kb) * 32 + g * 4);
                int cr0 = 2 * t, cr1 = 2 * t + 1;
                af[(basef + (cr0 & 3)) * 4 + half + 2 * (cr0 >> 2)] =
                    cvtf(o[d][2 * half    ] * inv);
                af[(basef + (cr1 & 3)) * 4 + half + 2 * (cr1 >> 2)] =
                    cvtf(o[d][2 * half + 1] * inv);
            }
        }
    }
}

// ---------------------------------------------------------------------------
extern "C" void kernel_launch(void* const* d_in, const int* in_sizes, int n_in,
                              void* d_out, int out_size) {
    const float* x     = (const float*)d_in[0];
    const float* Wqkv  = (const float*)d_in[1];
    const float* bqkv  = (const float*)d_in[2];
    const float* Wproj = (const float*)d_in[3];
    const float* bproj = (const float*)d_in[4];
    float* out = (float*)d_out;

    float *af, *wqkvF, *wprojF, *Qf, *Kf, *Vf;
    cudaGetSymbolAddress((void**)&af,     g_af);
    cudaGetSymbolAddress((void**)&wqkvF,  g_wqkvF);
    cudaGetSymbolAddress((void**)&wprojF, g_wprojF);
    cudaGetSymbolAddress((void**)&Qf,     g_Qf);
    cudaGetSymbolAddress((void**)&Kf,     g_Kf);
    cudaGetSymbolAddress((void**)&Vf,     g_Vf);

    cudaFuncSetAttribute(gemm_frag_kernel,
                         cudaFuncAttributeMaxDynamicSharedMemorySize, GEMM_SMEM);
    cudaFuncSetAttribute(attn_v4_kernel,
                         cudaFuncAttributeMaxDynamicSharedMemorySize, ATT_SMEM);

    // 0) GEMM input prep
    prep_a_frag<<<(M_ * K_ / 4) / 256, 256>>>(x, af);
    prep_b_frag<<<(QKV_N * K_ / 2) / 256, 256>>>(Wqkv, wqkvF, QKV_N);
    prep_b_frag<<<(C_ * K_ / 2) / 256, 256>>>(Wproj, wprojF, C_);

    // 1) QKV projection, fused epilogue -> Qf/Kf/Vf fragment arrays
    {
        dim3 grid(QKV_N / 128, M_ / 128);
        gemm_frag_kernel<<<grid, 256, GEMM_SMEM>>>(
            af, wqkvF, bqkv, nullptr, Qf, Kf, Vf, QKV_N, 1);
    }

    // 2) causal flash attention (writes proj A-fragments directly)
    {
        dim3 grid(T_ / 128, H_, B_);
        attn_v4_kernel<<<grid, 256, ATT_SMEM>>>(Qf, Kf, Vf, af);
    }

    // 3) output projection (full fp32 out)
    {
        dim3 grid(C_ / 128, M_ / 128);
        gemm_frag_kernel<<<grid, 256, GEMM_SMEM>>>(
            af, wprojF, bproj, out, nullptr, nullptr, nullptr, C_, 0);
    }
}